// round 1
// baseline (speedup 1.0000x reference)
#include <cuda_runtime.h>
#include <math.h>

#define NN 50000
#define NE 800000
#define FI 256
#define NH 8
#define HD 64
#define C1 512          // NH*HD
#define NC 40
#define LRELU_SLOPE 0.2f

// ---------------- static scratch (no allocs allowed) ----------------
__device__ float g_H1[(size_t)NN * C1];     // layer-1 features per head (concat layout)
__device__ float g_OUT1[(size_t)NN * C1];   // layer-1 attention output
__device__ float g_ASRC1[NN * NH];
__device__ float g_ATGT1[NN * NH];
__device__ float g_DEN1[NN * NH];
__device__ float g_EV1[(size_t)NE * NH];
__device__ float g_H2[NN * NC];
__device__ float g_OUT2[NN * NC];
__device__ float g_ASRC2[NN];
__device__ float g_ATGT2[NN];
__device__ float g_DEN2[NN];
__device__ float g_EV2[NE];
__device__ int   g_CNT[NN];
__device__ int   g_OFFS[NN + 1];
__device__ int   g_CURSOR[NN];
__device__ int   g_ORDER[NE];
__device__ int   g_AUX[128];

// ---------------- helpers ----------------
__device__ __forceinline__ float lrelu(float v) { return v > 0.f ? v : LRELU_SLOPE * v; }
__device__ __forceinline__ float eluf(float v)  { return v > 0.f ? v : expm1f(v); }

__device__ __forceinline__ float wsum(float v) {
#pragma unroll
    for (int o = 16; o; o >>= 1) v += __shfl_xor_sync(0xffffffffu, v, o);
    return v;
}
__device__ __forceinline__ float wmax(float v) {
#pragma unroll
    for (int o = 16; o; o >>= 1) v = fmaxf(v, __shfl_xor_sync(0xffffffffu, v, o));
    return v;
}

// ---------------- zero init ----------------
__global__ void zero_all_kernel() {
    int i = blockIdx.x * blockDim.x + threadIdx.x;
    if (i < NN * NH) g_DEN1[i] = 0.f;
    if (i < NN) { g_DEN2[i] = 0.f; g_CNT[i] = 0; }
}

// ---------------- GEMM1: H1[N,512] = x[N,256] @ W1cat ----------------
// B[k][c] = W1[(c>>6)*FI*HD + k*HD + (c&63)]
__global__ __launch_bounds__(256) void gemm1_kernel(const float* __restrict__ A,
                                                    const float* __restrict__ W) {
    __shared__ float As[8][128];
    __shared__ float Bs[8][128];
    const int tid = threadIdx.x;
    const int bm = blockIdx.x * 128;
    const int bn = blockIdx.y * 128;

    const int arow = tid >> 1;            // 0..127
    const int acol = (tid & 1) << 2;      // 0 or 4
    const int brow = tid >> 5;            // 0..7  (k within tile)
    const int bcol = (tid & 31) << 2;     // 0..124

    const int gc = bn + bcol;
    const float* Bp = W + (gc >> 6) * (FI * HD) + (gc & 63) + brow * HD;
    const float* Ap = A + (size_t)(bm + arow) * FI + acol;
    const bool arow_ok = (bm + arow) < NN;

    float acc[8][8];
#pragma unroll
    for (int i = 0; i < 8; i++)
#pragma unroll
        for (int j = 0; j < 8; j++) acc[i][j] = 0.f;

    const int ty = tid >> 4, tx = tid & 15;

    for (int k0 = 0; k0 < FI; k0 += 8) {
        float4 av = arow_ok ? *(const float4*)Ap : make_float4(0.f, 0.f, 0.f, 0.f);
        Ap += 8;
        float4 bv = *(const float4*)Bp;
        Bp += 8 * HD;

        As[acol + 0][arow] = av.x;
        As[acol + 1][arow] = av.y;
        As[acol + 2][arow] = av.z;
        As[acol + 3][arow] = av.w;
        *(float4*)&Bs[brow][bcol] = bv;
        __syncthreads();

#pragma unroll
        for (int kk = 0; kk < 8; kk++) {
            float ra[8], rb[8];
            *(float4*)&ra[0] = *(const float4*)&As[kk][ty * 8];
            *(float4*)&ra[4] = *(const float4*)&As[kk][ty * 8 + 4];
            *(float4*)&rb[0] = *(const float4*)&Bs[kk][tx * 8];
            *(float4*)&rb[4] = *(const float4*)&Bs[kk][tx * 8 + 4];
#pragma unroll
            for (int i = 0; i < 8; i++)
#pragma unroll
                for (int j = 0; j < 8; j++) acc[i][j] += ra[i] * rb[j];
        }
        __syncthreads();
    }

#pragma unroll
    for (int i = 0; i < 8; i++) {
        int r = bm + ty * 8 + i;
        if (r < NN) {
            float* Cp = g_H1 + (size_t)r * C1 + bn + tx * 8;
            *(float4*)Cp       = make_float4(acc[i][0], acc[i][1], acc[i][2], acc[i][3]);
            *(float4*)(Cp + 4) = make_float4(acc[i][4], acc[i][5], acc[i][6], acc[i][7]);
        }
    }
}

// ---------------- alpha1: per-node per-head dots with a1 ----------------
__global__ void alpha1_kernel(const float* __restrict__ a1) {
    int w = (blockIdx.x * blockDim.x + threadIdx.x) >> 5;
    int lane = threadIdx.x & 31;
    if (w >= NN) return;
    int h = lane >> 2, j = lane & 3;   // 8 lanes... 4 lanes per head
    const float* row = g_H1 + (size_t)w * C1 + h * HD + j * 16;
    const float* av  = a1 + h * (2 * HD) + j * 16;
    const float* tv  = av + HD;
    float ps = 0.f, pt = 0.f;
#pragma unroll
    for (int i = 0; i < 16; i += 4) {
        float4 v  = *(const float4*)(row + i);
        float4 sa = *(const float4*)(av + i);
        float4 ta = *(const float4*)(tv + i);
        ps += v.x * sa.x + v.y * sa.y + v.z * sa.z + v.w * sa.w;
        pt += v.x * ta.x + v.y * ta.y + v.z * ta.z + v.w * ta.w;
    }
    ps += __shfl_xor_sync(0xffffffffu, ps, 1);
    ps += __shfl_xor_sync(0xffffffffu, ps, 2);
    pt += __shfl_xor_sync(0xffffffffu, pt, 1);
    pt += __shfl_xor_sync(0xffffffffu, pt, 2);
    if (j == 0) {
        g_ASRC1[w * NH + h] = ps;
        g_ATGT1[w * NH + h] = pt;
    }
}

// ---------------- edge1: ev + denom + src histogram ----------------
__global__ void edge1_kernel(const int* __restrict__ src, const int* __restrict__ tgt) {
    int e = blockIdx.x * blockDim.x + threadIdx.x;
    if (e >= NE) return;
    int s = src[e], t = tgt[e];
    atomicAdd(&g_CNT[s], 1);
    float4 a0 = *(const float4*)&g_ASRC1[s * NH];
    float4 a1v = *(const float4*)&g_ASRC1[s * NH + 4];
    float4 t0 = *(const float4*)&g_ATGT1[t * NH];
    float4 t1 = *(const float4*)&g_ATGT1[t * NH + 4];
    float vs[8] = {a0.x + t0.x, a0.y + t0.y, a0.z + t0.z, a0.w + t0.w,
                   a1v.x + t1.x, a1v.y + t1.y, a1v.z + t1.z, a1v.w + t1.w};
    float ev[8];
#pragma unroll
    for (int h = 0; h < 8; h++) {
        ev[h] = expf(lrelu(vs[h]));
        atomicAdd(&g_DEN1[s * NH + h], ev[h]);
    }
    *(float4*)&g_EV1[(size_t)e * NH]     = make_float4(ev[0], ev[1], ev[2], ev[3]);
    *(float4*)&g_EV1[(size_t)e * NH + 4] = make_float4(ev[4], ev[5], ev[6], ev[7]);
}

// ---------------- counting-sort scan ----------------
#define SBLK 512
#define NBLK 98   // 98*512 = 50176 >= NN

__global__ void scan_block_kernel() {
    __shared__ int sh[SBLK];
    int t = threadIdx.x;
    int i = blockIdx.x * SBLK + t;
    int v = (i < NN) ? g_CNT[i] : 0;
    sh[t] = v;
    __syncthreads();
#pragma unroll
    for (int off = 1; off < SBLK; off <<= 1) {
        int add = (t >= off) ? sh[t - off] : 0;
        __syncthreads();
        sh[t] += add;
        __syncthreads();
    }
    if (i < NN) g_OFFS[i] = sh[t] - v;     // exclusive within block
    if (t == SBLK - 1) g_AUX[blockIdx.x] = sh[SBLK - 1];
}

__global__ void scan_aux_kernel() {
    int run = 0;
    for (int b = 0; b < NBLK; b++) { int t = g_AUX[b]; g_AUX[b] = run; run += t; }
}

__global__ void scan_add_kernel() {
    int t = threadIdx.x;
    int i = blockIdx.x * SBLK + t;
    if (i < NN) {
        int v = g_OFFS[i] + g_AUX[blockIdx.x];
        g_OFFS[i] = v;
        g_CURSOR[i] = v;
    }
    if (i == 0) g_OFFS[NN] = NE;
}

__global__ void sort_kernel(const int* __restrict__ src) {
    int e = blockIdx.x * blockDim.x + threadIdx.x;
    if (e >= NE) return;
    int s = src[e];
    int pos = atomicAdd(&g_CURSOR[s], 1);
    g_ORDER[pos] = e;
}

// ---------------- gather1: OUT1[n] = sum_e att * H1[tgt] ----------------
__global__ void gather1_kernel(const int* __restrict__ tgt) {
    int w = (blockIdx.x * blockDim.x + threadIdx.x) >> 5;
    int lane = threadIdx.x & 31;
    if (w >= NN) return;
    int beg = g_OFFS[w], end = g_OFFS[w + 1];
    int half = lane >> 4;
    float rden[4];
#pragma unroll
    for (int g = 0; g < 4; g++) {
        int h = g * 2 + half;
        rden[g] = 1.f / (g_DEN1[w * NH + h] + 1e-10f);
    }
    float4 acc[4];
#pragma unroll
    for (int g = 0; g < 4; g++) acc[g] = make_float4(0.f, 0.f, 0.f, 0.f);

    for (int i = beg; i < end; i++) {
        int e = g_ORDER[i];
        int t = tgt[e];
        const float* hrow = g_H1 + (size_t)t * C1;
        const float* evp = g_EV1 + (size_t)e * NH;
#pragma unroll
        for (int g = 0; g < 4; g++) {
            float att = evp[g * 2 + half] * rden[g];
            float4 v = *(const float4*)(hrow + g * 128 + lane * 4);
            acc[g].x += att * v.x;
            acc[g].y += att * v.y;
            acc[g].z += att * v.z;
            acc[g].w += att * v.w;
        }
    }
    float* orow = g_OUT1 + (size_t)w * C1;
#pragma unroll
    for (int g = 0; g < 4; g++) *(float4*)(orow + g * 128 + lane * 4) = acc[g];
}

// ---------------- GEMM2: H2[N,40] = ELU(OUT1 + b1) @ W2[512,40] ----------------
__global__ __launch_bounds__(128) void gemm2_kernel(const float* __restrict__ W2,
                                                    const float* __restrict__ b1) {
    __shared__ float As[16][128];
    __shared__ float Bs[16][NC];
    int tid = threadIdx.x;
    int bm = blockIdx.x * 128;
    int ar = tid >> 2;             // 0..31
    int akc = (tid & 3) << 2;      // 0,4,8,12
    int ty = tid >> 3, tx = tid & 7;

    float acc[8][5];
#pragma unroll
    for (int i = 0; i < 8; i++)
#pragma unroll
        for (int j = 0; j < 5; j++) acc[i][j] = 0.f;

    for (int k0 = 0; k0 < C1; k0 += 16) {
#pragma unroll
        for (int i = 0; i < 4; i++) {
            int r = ar + i * 32;
            int gr = bm + r;
            float4 v = (gr < NN) ? *(const float4*)&g_OUT1[(size_t)gr * C1 + k0 + akc]
                                 : make_float4(0.f, 0.f, 0.f, 0.f);
            float4 bb = *(const float4*)&b1[k0 + akc];
            As[akc + 0][r] = eluf(v.x + bb.x);
            As[akc + 1][r] = eluf(v.y + bb.y);
            As[akc + 2][r] = eluf(v.z + bb.z);
            As[akc + 3][r] = eluf(v.w + bb.w);
        }
#pragma unroll
        for (int idx = tid; idx < 16 * NC; idx += 128) {
            int k = idx / NC, c = idx % NC;
            Bs[k][c] = W2[(k0 + k) * NC + c];
        }
        __syncthreads();
#pragma unroll
        for (int kk = 0; kk < 16; kk++) {
            float ra[8];
            *(float4*)&ra[0] = *(const float4*)&As[kk][ty * 8];
            *(float4*)&ra[4] = *(const float4*)&As[kk][ty * 8 + 4];
            float rb[5];
#pragma unroll
            for (int j = 0; j < 5; j++) rb[j] = Bs[kk][tx * 5 + j];
#pragma unroll
            for (int i = 0; i < 8; i++)
#pragma unroll
                for (int j = 0; j < 5; j++) acc[i][j] += ra[i] * rb[j];
        }
        __syncthreads();
    }
#pragma unroll
    for (int i = 0; i < 8; i++) {
        int r = bm + ty * 8 + i;
        if (r < NN) {
#pragma unroll
            for (int j = 0; j < 5; j++) g_H2[r * NC + tx * 5 + j] = acc[i][j];
        }
    }
}

// ---------------- alpha2 ----------------
__global__ void alpha2_kernel(const float* __restrict__ a2) {
    int w = (blockIdx.x * blockDim.x + threadIdx.x) >> 5;
    int lane = threadIdx.x & 31;
    if (w >= NN) return;
    float v1 = g_H2[w * NC + lane];
    bool has2 = lane < 8;
    float v2 = has2 ? g_H2[w * NC + 32 + lane] : 0.f;
    float s = v1 * a2[lane] + (has2 ? v2 * a2[32 + lane] : 0.f);
    float t = v1 * a2[NC + lane] + (has2 ? v2 * a2[NC + 32 + lane] : 0.f);
    s = wsum(s);
    t = wsum(t);
    if (lane == 0) { g_ASRC2[w] = s; g_ATGT2[w] = t; }
}

// ---------------- edge2 ----------------
__global__ void edge2_kernel(const int* __restrict__ src, const int* __restrict__ tgt) {
    int e = blockIdx.x * blockDim.x + threadIdx.x;
    if (e >= NE) return;
    int s = src[e], t = tgt[e];
    float ev = expf(lrelu(g_ASRC2[s] + g_ATGT2[t]));
    atomicAdd(&g_DEN2[s], ev);
    g_EV2[e] = ev;
}

// ---------------- gather2 ----------------
__global__ void gather2_kernel(const int* __restrict__ tgt) {
    int w = (blockIdx.x * blockDim.x + threadIdx.x) >> 5;
    int lane = threadIdx.x & 31;
    if (w >= NN) return;
    int beg = g_OFFS[w], end = g_OFFS[w + 1];
    float rden = 1.f / (g_DEN2[w] + 1e-10f);
    bool has2 = lane < 8;
    float acc1 = 0.f, acc2 = 0.f;
    for (int i = beg; i < end; i++) {
        int e = g_ORDER[i];
        int t = tgt[e];
        float att = g_EV2[e] * rden;
        acc1 += att * g_H2[t * NC + lane];
        if (has2) acc2 += att * g_H2[t * NC + 32 + lane];
    }
    g_OUT2[w * NC + lane] = acc1;
    if (has2) g_OUT2[w * NC + 32 + lane] = acc2;
}

// ---------------- log_softmax ----------------
__global__ void logsm_kernel(const float* __restrict__ b2, float* __restrict__ out) {
    int w = (blockIdx.x * blockDim.x + threadIdx.x) >> 5;
    int lane = threadIdx.x & 31;
    if (w >= NN) return;
    float v1 = g_OUT2[w * NC + lane] + b2[lane];
    bool has2 = lane < 8;
    float v2 = has2 ? (g_OUT2[w * NC + 32 + lane] + b2[32 + lane]) : -3.0e38f;
    float m = wmax(fmaxf(v1, v2));
    float ssum = expf(v1 - m) + (has2 ? expf(v2 - m) : 0.f);
    ssum = wsum(ssum);
    float l = logf(ssum);
    out[w * NC + lane] = v1 - m - l;
    if (has2) out[w * NC + 32 + lane] = v2 - m - l;
}

// ---------------- launch ----------------
extern "C" void kernel_launch(void* const* d_in, const int* in_sizes, int n_in,
                              void* d_out, int out_size) {
    const float* x  = (const float*)d_in[0];
    const int*   el = (const int*)d_in[1];
    const float* W1 = (const float*)d_in[2];
    const float* a1 = (const float*)d_in[3];
    const float* b1 = (const float*)d_in[4];
    const float* W2 = (const float*)d_in[5];
    const float* a2 = (const float*)d_in[6];
    const float* b2 = (const float*)d_in[7];
    float* out = (float*)d_out;
    const int* src = el;
    const int* tgt = el + NE;

    zero_all_kernel<<<(NN * NH + 255) / 256, 256>>>();

    dim3 g1((NN + 127) / 128, C1 / 128);
    gemm1_kernel<<<g1, 256>>>(x, W1);

    int warp_grid = (NN * 32 + 255) / 256;   // warp per node
    alpha1_kernel<<<warp_grid, 256>>>(a1);

    edge1_kernel<<<(NE + 255) / 256, 256>>>(src, tgt);

    scan_block_kernel<<<NBLK, SBLK>>>();
    scan_aux_kernel<<<1, 1>>>();
    scan_add_kernel<<<NBLK, SBLK>>>();
    sort_kernel<<<(NE + 255) / 256, 256>>>(src);

    gather1_kernel<<<warp_grid, 256>>>(tgt);

    gemm2_kernel<<<(NN + 127) / 128, 128>>>(W2, b1);
    alpha2_kernel<<<warp_grid, 256>>>(a2);
    edge2_kernel<<<(NE + 255) / 256, 256>>>(src, tgt);
    gather2_kernel<<<warp_grid, 256>>>(tgt);
    logsm_kernel<<<warp_grid, 256>>>(b2, out);
}

// round 3
// speedup vs baseline: 1.0467x; 1.0467x over previous
#include <cuda_runtime.h>
#include <cuda_bf16.h>
#include <math.h>

#define NN 50000
#define NE 800000
#define FI 256
#define NH 8
#define HD 64
#define C1 512
#define NC 40
#define LRELU_SLOPE 0.2f

// ---------------- static scratch ----------------
__device__ float g_H1[(size_t)NN * C1];
__device__ float g_OUT1[(size_t)NN * C1];
__device__ float g_ASRC1[NN * NH];
__device__ float g_ATGT1[NN * NH];
__device__ float g_EV1[(size_t)NE * NH];
__device__ float g_H2[NN * NC];
__device__ float g_OUT2[NN * NC];
__device__ float g_ASRC2[NN];
__device__ float g_ATGT2[NN];
__device__ float g_EV2[NE];
__device__ int   g_CNT[NN];
__device__ int   g_OFFS[NN + 1];
__device__ int   g_CURSOR[NN];
__device__ int   g_ORDER[NE];
__device__ int   g_AUX[128];

// ---------------- helpers ----------------
__device__ __forceinline__ float lrelu(float v) { return v > 0.f ? v : LRELU_SLOPE * v; }
__device__ __forceinline__ float eluf(float v)  { return v > 0.f ? v : expm1f(v); }

__device__ __forceinline__ float wsum(float v) {
#pragma unroll
    for (int o = 16; o; o >>= 1) v += __shfl_xor_sync(0xffffffffu, v, o);
    return v;
}
__device__ __forceinline__ float wmax(float v) {
#pragma unroll
    for (int o = 16; o; o >>= 1) v = fmaxf(v, __shfl_xor_sync(0xffffffffu, v, o));
    return v;
}

__device__ __forceinline__ unsigned smem_u32(const void* p) {
    return (unsigned)__cvta_generic_to_shared(p);
}

__device__ __forceinline__ void ldm4(unsigned& r0, unsigned& r1, unsigned& r2, unsigned& r3,
                                     unsigned addr) {
    asm volatile("ldmatrix.sync.aligned.m8n8.x4.shared.b16 {%0,%1,%2,%3}, [%4];"
                 : "=r"(r0), "=r"(r1), "=r"(r2), "=r"(r3) : "r"(addr));
}

__device__ __forceinline__ void mma16816(float* c, const unsigned* a, const unsigned* b) {
    asm volatile("mma.sync.aligned.m16n8k16.row.col.f32.bf16.bf16.f32 "
                 "{%0,%1,%2,%3}, {%4,%5,%6,%7}, {%8,%9}, {%0,%1,%2,%3};"
                 : "+f"(c[0]), "+f"(c[1]), "+f"(c[2]), "+f"(c[3])
                 : "r"(a[0]), "r"(a[1]), "r"(a[2]), "r"(a[3]), "r"(b[0]), "r"(b[1]));
}

// pack two floats into (hi-bf16 pair, lo-bf16 pair) words
__device__ __forceinline__ void split2(float x, float y, unsigned& hw, unsigned& lw) {
    __nv_bfloat16 hx = __float2bfloat16(x);
    __nv_bfloat16 hy = __float2bfloat16(y);
    float rx = x - __bfloat162float(hx);
    float ry = y - __bfloat162float(hy);
    unsigned ux = (unsigned)__bfloat16_as_ushort(hx);
    unsigned uy = (unsigned)__bfloat16_as_ushort(hy);
    hw = ux | (uy << 16);
    unsigned vx = (unsigned)__bfloat16_as_ushort(__float2bfloat16(rx));
    unsigned vy = (unsigned)__bfloat16_as_ushort(__float2bfloat16(ry));
    lw = vx | (vy << 16);
}

// ---------------- zero init ----------------
__global__ void zero_all_kernel() {
    int i = blockIdx.x * blockDim.x + threadIdx.x;
    if (i < NN) g_CNT[i] = 0;
}

// ---------------- GEMM1 (bf16-split tensor core) + fused a1 dots ----------------
// H1[N,512] = x[N,256] @ Bcat,  Bcat[k][c] = W1[(c>>6)*FI*HD + k*HD + (c&63)]
// Block tile 128x128 (2 heads), BK=16, 8 warps (4m x 2n), warp tile 32x64.
__global__ __launch_bounds__(256) void gemm1_mma_kernel(const float* __restrict__ A,
                                                        const float* __restrict__ W,
                                                        const float* __restrict__ a1p) {
    // packed bf16 pairs: [row][kpair], row stride 12 words = 48 bytes
    __shared__ unsigned Ah[128][12];
    __shared__ unsigned Al[128][12];
    __shared__ unsigned Bh[128][12];   // [col][kpair]
    __shared__ unsigned Bl[128][12];

    const int tid  = threadIdx.x;
    const int lane = tid & 31;
    const int wid  = tid >> 5;
    const int wm   = wid >> 1;       // 0..3
    const int wn   = wid & 1;        // 0..1
    const int bm   = blockIdx.x * 128;
    const int bn   = blockIdx.y * 128;

    float acc[2][8][4];
#pragma unroll
    for (int i = 0; i < 2; i++)
#pragma unroll
        for (int j = 0; j < 8; j++)
#pragma unroll
            for (int k = 0; k < 4; k++) acc[i][j][k] = 0.f;

    const unsigned aBaseH = smem_u32(Ah);
    const unsigned aBaseL = smem_u32(Al);
    const unsigned bBaseH = smem_u32(Bh);
    const unsigned bBaseL = smem_u32(Bl);

    // ldmatrix addresses (bytes): row stride 48
    unsigned aadrH[2];
    unsigned aadrL[2];
#pragma unroll
    for (int mt = 0; mt < 2; mt++) {
        int r = wm * 32 + mt * 16 + (lane & 15);
        int cb = (lane >> 4) * 16;              // 0 or 16 bytes (8 halves)
        aadrH[mt] = aBaseH + r * 48 + cb;
        aadrL[mt] = aBaseL + r * 48 + cb;
    }
    unsigned badrH[4];
    unsigned badrL[4];
#pragma unroll
    for (int np = 0; np < 4; np++) {
        int r = wn * 64 + np * 16 + ((lane >> 4) << 3) + (lane & 7);
        int cb = ((lane >> 3) & 1) * 16;
        badrH[np] = bBaseH + r * 48 + cb;
        badrL[np] = bBaseL + r * 48 + cb;
    }

    for (int it = 0; it < FI / 16; ++it) {
        const int k0 = it * 16;
        // A tile: 128 rows x 16 k, 512 float4 loads by 512 "items" (256 threads x2)
#pragma unroll
        for (int u = 0; u < 2; ++u) {
            int i = tid + u * 256;
            int row = i >> 2;
            int kq  = (i & 3) << 2;            // 0,4,8,12
            int gr  = bm + row;
            float4 v = (gr < NN) ? *(const float4*)(A + (size_t)gr * FI + k0 + kq)
                                 : make_float4(0.f, 0.f, 0.f, 0.f);
            unsigned hw0, lw0, hw1, lw1;
            split2(v.x, v.y, hw0, lw0);
            split2(v.z, v.w, hw1, lw1);
            int kp = kq >> 1;                  // word index
            Ah[row][kp]     = hw0;
            Al[row][kp]     = lw0;
            Ah[row][kp + 1] = hw1;
            Al[row][kp + 1] = lw1;
        }
        // B tile: 16 k x 128 cols, stored [col][k]
#pragma unroll
        for (int u = 0; u < 2; ++u) {
            int i = tid + u * 256;
            int k  = i >> 5;                   // 0..15
            int cq = (i & 31) << 2;            // 0..124
            int gc = bn + cq;
            const float* wp = W + (size_t)(gc >> 6) * (FI * HD) + (size_t)(k0 + k) * HD + (gc & 63);
            float4 v = *(const float4*)wp;
            float vv0 = v.x, vv1 = v.y, vv2 = v.z, vv3 = v.w;
            // scalar stores into 4 different col rows at word k>>1, half k&1
            float vals[4];
            vals[0] = vv0; vals[1] = vv1; vals[2] = vv2; vals[3] = vv3;
#pragma unroll
            for (int j = 0; j < 4; j++) {
                __nv_bfloat16 hb = __float2bfloat16(vals[j]);
                float res = vals[j] - __bfloat162float(hb);
                unsigned hu = (unsigned)__bfloat16_as_ushort(hb);
                unsigned lu = (unsigned)__bfloat16_as_ushort(__float2bfloat16(res));
                int word = k >> 1;
                int sh = (k & 1) * 16;
                unsigned mask = 0xFFFFu << sh;
                // two threads never write same (col,word) half: each (col,k) unique
                // do read-modify-write free via 16-bit stores:
                unsigned short* ph = (unsigned short*)&Bh[cq + j][word];
                unsigned short* pl = (unsigned short*)&Bl[cq + j][word];
                ph[k & 1] = (unsigned short)hu;
                pl[k & 1] = (unsigned short)lu;
                (void)mask; (void)sh;
            }
        }
        __syncthreads();

        unsigned ah[2][4];
        unsigned al[2][4];
#pragma unroll
        for (int mt = 0; mt < 2; mt++) {
            ldm4(ah[mt][0], ah[mt][1], ah[mt][2], ah[mt][3], aadrH[mt]);
            ldm4(al[mt][0], al[mt][1], al[mt][2], al[mt][3], aadrL[mt]);
        }
#pragma unroll
        for (int np = 0; np < 4; np++) {
            unsigned bh[4];
            unsigned bl[4];
            ldm4(bh[0], bh[1], bh[2], bh[3], badrH[np]);
            ldm4(bl[0], bl[1], bl[2], bl[3], badrL[np]);
#pragma unroll
            for (int mt = 0; mt < 2; mt++) {
                mma16816(acc[mt][np * 2],     ah[mt], bh);
                mma16816(acc[mt][np * 2],     ah[mt], bl);
                mma16816(acc[mt][np * 2],     al[mt], bh);
                mma16816(acc[mt][np * 2 + 1], ah[mt], bh + 2);
                mma16816(acc[mt][np * 2 + 1], ah[mt], bl + 2);
                mma16816(acc[mt][np * 2 + 1], al[mt], bh + 2);
            }
        }
        __syncthreads();
    }

    // ---- write H1 ----
#pragma unroll
    for (int mt = 0; mt < 2; mt++) {
        int r = bm + wm * 32 + mt * 16 + (lane >> 2);
        int c = bn + wn * 64 + (lane & 3) * 2;
#pragma unroll
        for (int nt = 0; nt < 8; nt++) {
            if (r < NN) {
                float2 v0;
                v0.x = acc[mt][nt][0];
                v0.y = acc[mt][nt][1];
                *(float2*)&g_H1[(size_t)r * C1 + c + nt * 8] = v0;
            }
            if (r + 8 < NN) {
                float2 v1;
                v1.x = acc[mt][nt][2];
                v1.y = acc[mt][nt][3];
                *(float2*)&g_H1[(size_t)(r + 8) * C1 + c + nt * 8] = v1;
            }
        }
    }

    // ---- fused a1 dots: warp wn owns head h over its 64 cols ----
    const int hh = blockIdx.y * 2 + wn;
    const float* av = a1p + hh * (2 * HD);
    const float* tv = av + HD;
    float sdot[4];
    float tdot[4];
#pragma unroll
    for (int i = 0; i < 4; i++) { sdot[i] = 0.f; tdot[i] = 0.f; }
#pragma unroll
    for (int mt = 0; mt < 2; mt++) {
#pragma unroll
        for (int nt = 0; nt < 8; nt++) {
            int cip = nt * 8 + (lane & 3) * 2;
            float a0 = __ldg(av + cip);
            float a1e = __ldg(av + cip + 1);
            float t0 = __ldg(tv + cip);
            float t1e = __ldg(tv + cip + 1);
            sdot[mt * 2 + 0] += acc[mt][nt][0] * a0 + acc[mt][nt][1] * a1e;
            tdot[mt * 2 + 0] += acc[mt][nt][0] * t0 + acc[mt][nt][1] * t1e;
            sdot[mt * 2 + 1] += acc[mt][nt][2] * a0 + acc[mt][nt][3] * a1e;
            tdot[mt * 2 + 1] += acc[mt][nt][2] * t0 + acc[mt][nt][3] * t1e;
        }
    }
#pragma unroll
    for (int i = 0; i < 4; i++) {
        sdot[i] += __shfl_xor_sync(0xffffffffu, sdot[i], 1);
        sdot[i] += __shfl_xor_sync(0xffffffffu, sdot[i], 2);
        tdot[i] += __shfl_xor_sync(0xffffffffu, tdot[i], 1);
        tdot[i] += __shfl_xor_sync(0xffffffffu, tdot[i], 2);
    }
    if ((lane & 3) == 0) {
#pragma unroll
        for (int mt = 0; mt < 2; mt++) {
#pragma unroll
            for (int hb = 0; hb < 2; hb++) {
                int r = bm + wm * 32 + mt * 16 + (lane >> 2) + hb * 8;
                if (r < NN) {
                    g_ASRC1[r * NH + hh] = sdot[mt * 2 + hb];
                    g_ATGT1[r * NH + hh] = tdot[mt * 2 + hb];
                }
            }
        }
    }
}

// ---------------- edge1: ev + src histogram ----------------
__global__ void edge1_kernel(const int* __restrict__ src, const int* __restrict__ tgt) {
    int e = blockIdx.x * blockDim.x + threadIdx.x;
    if (e >= NE) return;
    int s = src[e];
    int t = tgt[e];
    atomicAdd(&g_CNT[s], 1);
    float4 s0 = *(const float4*)&g_ASRC1[s * NH];
    float4 s1 = *(const float4*)&g_ASRC1[s * NH + 4];
    float4 t0 = *(const float4*)&g_ATGT1[t * NH];
    float4 t1 = *(const float4*)&g_ATGT1[t * NH + 4];
    float4 e0;
    float4 e1;
    e0.x = expf(lrelu(s0.x + t0.x));
    e0.y = expf(lrelu(s0.y + t0.y));
    e0.z = expf(lrelu(s0.z + t0.z));
    e0.w = expf(lrelu(s0.w + t0.w));
    e1.x = expf(lrelu(s1.x + t1.x));
    e1.y = expf(lrelu(s1.y + t1.y));
    e1.z = expf(lrelu(s1.z + t1.z));
    e1.w = expf(lrelu(s1.w + t1.w));
    *(float4*)&g_EV1[(size_t)e * NH]     = e0;
    *(float4*)&g_EV1[(size_t)e * NH + 4] = e1;
}

// ---------------- counting-sort scan ----------------
#define SBLK 512
#define NBLK 98

__global__ void scan_block_kernel() {
    __shared__ int sh[SBLK];
    int t = threadIdx.x;
    int i = blockIdx.x * SBLK + t;
    int v = (i < NN) ? g_CNT[i] : 0;
    sh[t] = v;
    __syncthreads();
#pragma unroll
    for (int off = 1; off < SBLK; off <<= 1) {
        int add = (t >= off) ? sh[t - off] : 0;
        __syncthreads();
        sh[t] += add;
        __syncthreads();
    }
    if (i < NN) g_OFFS[i] = sh[t] - v;
    if (t == SBLK - 1) g_AUX[blockIdx.x] = sh[SBLK - 1];
}

__global__ void scan_aux_kernel() {
    int run = 0;
    for (int b = 0; b < NBLK; b++) {
        int t = g_AUX[b];
        g_AUX[b] = run;
        run += t;
    }
}

__global__ void scan_add_kernel() {
    int t = threadIdx.x;
    int i = blockIdx.x * SBLK + t;
    if (i < NN) {
        int v = g_OFFS[i] + g_AUX[blockIdx.x];
        g_OFFS[i] = v;
        g_CURSOR[i] = v;
    }
    if (i == 0) g_OFFS[NN] = NE;
}

__global__ void sort_kernel(const int* __restrict__ src) {
    int e = blockIdx.x * blockDim.x + threadIdx.x;
    if (e >= NE) return;
    int s = src[e];
    int pos = atomicAdd(&g_CURSOR[s], 1);
    g_ORDER[pos] = e;
}

// ---------------- gather1 ----------------
__global__ void gather1_kernel(const int* __restrict__ tgt) {
    int w = (blockIdx.x * blockDim.x + threadIdx.x) >> 5;
    int lane = threadIdx.x & 31;
    if (w >= NN) return;
    int beg = g_OFFS[w];
    int end = g_OFFS[w + 1];
    int hsel = lane >> 4;      // 0 or 1
    float den[4];
    float4 acc[4];
#pragma unroll
    for (int g = 0; g < 4; g++) {
        den[g] = 0.f;
        acc[g] = make_float4(0.f, 0.f, 0.f, 0.f);
    }
    for (int i = beg; i < end; i++) {
        int e = g_ORDER[i];
        int t = tgt[e];
        const float* hrow = g_H1 + (size_t)t * C1;
        const float* evp = g_EV1 + (size_t)e * NH;
#pragma unroll
        for (int g = 0; g < 4; g++) {
            float ev = evp[g * 2 + hsel];
            den[g] += ev;
            float4 v = *(const float4*)(hrow + g * 128 + lane * 4);
            acc[g].x += ev * v.x;
            acc[g].y += ev * v.y;
            acc[g].z += ev * v.z;
            acc[g].w += ev * v.w;
        }
    }
    float* orow = g_OUT1 + (size_t)w * C1;
#pragma unroll
    for (int g = 0; g < 4; g++) {
        float r = 1.f / (den[g] + 1e-10f);
        float4 o;
        o.x = acc[g].x * r;
        o.y = acc[g].y * r;
        o.z = acc[g].z * r;
        o.w = acc[g].w * r;
        *(float4*)(orow + g * 128 + lane * 4) = o;
    }
}

// ---------------- GEMM2 ----------------
__global__ __launch_bounds__(128) void gemm2_kernel(const float* __restrict__ W2,
                                                    const float* __restrict__ b1) {
    __shared__ float As[16][128];
    __shared__ float Bs[16][NC];
    int tid = threadIdx.x;
    int bm = blockIdx.x * 128;
    int ar = tid >> 2;
    int akc = (tid & 3) << 2;
    int ty = tid >> 3;
    int tx = tid & 7;

    float acc[8][5];
#pragma unroll
    for (int i = 0; i < 8; i++)
#pragma unroll
        for (int j = 0; j < 5; j++) acc[i][j] = 0.f;

    for (int k0 = 0; k0 < C1; k0 += 16) {
#pragma unroll
        for (int i = 0; i < 4; i++) {
            int r = ar + i * 32;
            int gr = bm + r;
            float4 v = (gr < NN) ? *(const float4*)&g_OUT1[(size_t)gr * C1 + k0 + akc]
                                 : make_float4(0.f, 0.f, 0.f, 0.f);
            float4 bb = *(const float4*)&b1[k0 + akc];
            As[akc + 0][r] = eluf(v.x + bb.x);
            As[akc + 1][r] = eluf(v.y + bb.y);
            As[akc + 2][r] = eluf(v.z + bb.z);
            As[akc + 3][r] = eluf(v.w + bb.w);
        }
        for (int idx = tid; idx < 16 * NC; idx += 128) {
            int k = idx / NC;
            int c = idx % NC;
            Bs[k][c] = W2[(k0 + k) * NC + c];
        }
        __syncthreads();
#pragma unroll
        for (int kk = 0; kk < 16; kk++) {
            float ra[8];
            *(float4*)&ra[0] = *(const float4*)&As[kk][ty * 8];
            *(float4*)&ra[4] = *(const float4*)&As[kk][ty * 8 + 4];
            float rb[5];
#pragma unroll
            for (int j = 0; j < 5; j++) rb[j] = Bs[kk][tx * 5 + j];
#pragma unroll
            for (int i = 0; i < 8; i++)
#pragma unroll
                for (int j = 0; j < 5; j++) acc[i][j] += ra[i] * rb[j];
        }
        __syncthreads();
    }
#pragma unroll
    for (int i = 0; i < 8; i++) {
        int r = bm + ty * 8 + i;
        if (r < NN) {
#pragma unroll
            for (int j = 0; j < 5; j++) g_H2[r * NC + tx * 5 + j] = acc[i][j];
        }
    }
}

// ---------------- alpha2 ----------------
__global__ void alpha2_kernel(const float* __restrict__ a2) {
    int w = (blockIdx.x * blockDim.x + threadIdx.x) >> 5;
    int lane = threadIdx.x & 31;
    if (w >= NN) return;
    float v1 = g_H2[w * NC + lane];
    bool has2 = lane < 8;
    float v2 = has2 ? g_H2[w * NC + 32 + lane] : 0.f;
    float s = v1 * a2[lane] + (has2 ? v2 * a2[32 + lane] : 0.f);
    float t = v1 * a2[NC + lane] + (has2 ? v2 * a2[NC + 32 + lane] : 0.f);
    s = wsum(s);
    t = wsum(t);
    if (lane == 0) {
        g_ASRC2[w] = s;
        g_ATGT2[w] = t;
    }
}

// ---------------- edge2 ----------------
__global__ void edge2_kernel(const int* __restrict__ src, const int* __restrict__ tgt) {
    int e = blockIdx.x * blockDim.x + threadIdx.x;
    if (e >= NE) return;
    int s = src[e];
    int t = tgt[e];
    g_EV2[e] = expf(lrelu(g_ASRC2[s] + g_ATGT2[t]));
}

// ---------------- gather2 ----------------
__global__ void gather2_kernel(const int* __restrict__ tgt) {
    int w = (blockIdx.x * blockDim.x + threadIdx.x) >> 5;
    int lane = threadIdx.x & 31;
    if (w >= NN) return;
    int beg = g_OFFS[w];
    int end = g_OFFS[w + 1];
    bool has2 = lane < 8;
    float acc1 = 0.f;
    float acc2 = 0.f;
    float den = 0.f;
    for (int i = beg; i < end; i++) {
        int e = g_ORDER[i];
        int t = tgt[e];
        float ev = g_EV2[e];
        den += ev;
        acc1 += ev * g_H2[t * NC + lane];
        if (has2) acc2 += ev * g_H2[t * NC + 32 + lane];
    }
    float r = 1.f / (den + 1e-10f);
    g_OUT2[w * NC + lane] = acc1 * r;
    if (has2) g_OUT2[w * NC + 32 + lane] = acc2 * r;
}

// ---------------- log_softmax ----------------
__global__ void logsm_kernel(const float* __restrict__ b2, float* __restrict__ out) {
    int w = (blockIdx.x * blockDim.x + threadIdx.x) >> 5;
    int lane = threadIdx.x & 31;
    if (w >= NN) return;
    float v1 = g_OUT2[w * NC + lane] + b2[lane];
    bool has2 = lane < 8;
    float v2 = has2 ? (g_OUT2[w * NC + 32 + lane] + b2[32 + lane]) : -3.0e38f;
    float m = wmax(fmaxf(v1, v2));
    float ssum = expf(v1 - m) + (has2 ? expf(v2 - m) : 0.f);
    ssum = wsum(ssum);
    float l = logf(ssum);
    out[w * NC + lane] = v1 - m - l;
    if (has2) out[w * NC + 32 + lane] = v2 - m - l;
}

// ---------------- launch ----------------
extern "C" void kernel_launch(void* const* d_in, const int* in_sizes, int n_in,
                              void* d_out, int out_size) {
    const float* x  = (const float*)d_in[0];
    const int*   el = (const int*)d_in[1];
    const float* W1 = (const float*)d_in[2];
    const float* a1 = (const float*)d_in[3];
    const float* b1 = (const float*)d_in[4];
    const float* W2 = (const float*)d_in[5];
    const float* a2 = (const float*)d_in[6];
    const float* b2 = (const float*)d_in[7];
    float* out = (float*)d_out;
    const int* src = el;
    const int* tgt = el + NE;

    zero_all_kernel<<<(NN + 255) / 256, 256>>>();

    dim3 g1((NN + 127) / 128, C1 / 128);
    gemm1_mma_kernel<<<g1, 256>>>(x, W1, a1);

    edge1_kernel<<<(NE + 255) / 256, 256>>>(src, tgt);

    scan_block_kernel<<<NBLK, SBLK>>>();
    scan_aux_kernel<<<1, 1>>>();
    scan_add_kernel<<<NBLK, SBLK>>>();
    sort_kernel<<<(NE + 255) / 256, 256>>>(src);

    int warp_grid = (NN * 32 + 255) / 256;
    gather1_kernel<<<warp_grid, 256>>>(tgt);

    gemm2_kernel<<<(NN + 127) / 128, 128>>>(W2, b1);
    alpha2_kernel<<<warp_grid, 256>>>(a2);
    edge2_kernel<<<(NE + 255) / 256, 256>>>(src, tgt);
    gather2_kernel<<<warp_grid, 256>>>(tgt);
    logsm_kernel<<<warp_grid, 256>>>(b2, out);
}

// round 4
// speedup vs baseline: 1.4938x; 1.4272x over previous
#include <cuda_runtime.h>
#include <cuda_bf16.h>
#include <math.h>

#define NN 50000
#define NP 50176          // padded rows (multiple of 128)
#define NE 800000
#define FI 256
#define NH 8
#define HD 64
#define C1 512
#define NC 40
#define LRELU_SLOPE 0.2f

// ---------------- static scratch ----------------
__device__ float g_H1[(size_t)NN * C1];
__device__ float g_ASRC1[NN * NH];
__device__ float g_ATGT1[NN * NH];
__device__ float g_EV1[(size_t)NE * NH];
__device__ float g_H2[NN * NC];
__device__ float g_OUT2[NN * NC];
__device__ float g_ASRC2[NN];
__device__ float g_ATGT2[NN];
__device__ float g_EV2[NE];
__device__ int   g_CNT[NN];
__device__ int   g_OFFS[NN + 1];
__device__ int   g_CURSOR[NN];
__device__ int   g_ORDER[NE];
__device__ int   g_AUX[128];

// bf16-split operands (packed, 2 bf16 per unsigned where noted)
__device__ __align__(16) unsigned g_XH[(size_t)NP * FI / 2];
__device__ __align__(16) unsigned g_XL[(size_t)NP * FI / 2];
__device__ __align__(16) unsigned short g_W1TH[C1 * FI];   // [col512][k256]
__device__ __align__(16) unsigned short g_W1TL[C1 * FI];
__device__ __align__(16) unsigned short g_W2TH[NC * C1];   // [col40][k512]
__device__ __align__(16) unsigned short g_W2TL[NC * C1];
__device__ __align__(16) unsigned short g_EH[(size_t)NP * C1];  // ELU(OUT1+b1) hi
__device__ __align__(16) unsigned short g_EL[(size_t)NP * C1];  // lo

// ---------------- helpers ----------------
__device__ __forceinline__ float lrelu(float v) { return v > 0.f ? v : LRELU_SLOPE * v; }
__device__ __forceinline__ float eluf(float v)  { return v > 0.f ? v : expm1f(v); }

__device__ __forceinline__ float wsum(float v) {
#pragma unroll
    for (int o = 16; o; o >>= 1) v += __shfl_xor_sync(0xffffffffu, v, o);
    return v;
}
__device__ __forceinline__ float wmax(float v) {
#pragma unroll
    for (int o = 16; o; o >>= 1) v = fmaxf(v, __shfl_xor_sync(0xffffffffu, v, o));
    return v;
}

__device__ __forceinline__ unsigned smem_u32(const void* p) {
    return (unsigned)__cvta_generic_to_shared(p);
}

__device__ __forceinline__ void ldm4(unsigned& r0, unsigned& r1, unsigned& r2, unsigned& r3,
                                     unsigned addr) {
    asm volatile("ldmatrix.sync.aligned.m8n8.x4.shared.b16 {%0,%1,%2,%3}, [%4];"
                 : "=r"(r0), "=r"(r1), "=r"(r2), "=r"(r3) : "r"(addr));
}

__device__ __forceinline__ void mma16816(float* c, const unsigned* a, const unsigned* b) {
    asm volatile("mma.sync.aligned.m16n8k16.row.col.f32.bf16.bf16.f32 "
                 "{%0,%1,%2,%3}, {%4,%5,%6,%7}, {%8,%9}, {%0,%1,%2,%3};"
                 : "+f"(c[0]), "+f"(c[1]), "+f"(c[2]), "+f"(c[3])
                 : "r"(a[0]), "r"(a[1]), "r"(a[2]), "r"(a[3]), "r"(b[0]), "r"(b[1]));
}

__device__ __forceinline__ void split1(float x, unsigned short& h, unsigned short& l) {
    __nv_bfloat16 hb = __float2bfloat16(x);
    float r = x - __bfloat162float(hb);
    h = (unsigned short)__bfloat16_as_ushort(hb);
    l = (unsigned short)__bfloat16_as_ushort(__float2bfloat16(r));
}

__device__ __forceinline__ void split2(float x, float y, unsigned& hw, unsigned& lw) {
    unsigned short hx, lx, hy, ly;
    split1(x, hx, lx);
    split1(y, hy, ly);
    hw = (unsigned)hx | ((unsigned)hy << 16);
    lw = (unsigned)lx | ((unsigned)ly << 16);
}

// ---------------- init / prep ----------------
__global__ void zero_all_kernel() {
    int i = blockIdx.x * blockDim.x + threadIdx.x;
    if (i < NN) g_CNT[i] = 0;
    if (i < (NP - NN) * C1) {           // zero EH/EL pad rows
        g_EH[(size_t)NN * C1 + i] = 0;
        g_EL[(size_t)NN * C1 + i] = 0;
    }
}

__global__ void prep_x_kernel(const float* __restrict__ x) {
    int i = blockIdx.x * blockDim.x + threadIdx.x;   // float4 index over padded
    if (i >= NP * FI / 4) return;
    int row = i >> 6;
    float4 v = (row < NN) ? *(const float4*)(x + (size_t)i * 4)
                          : make_float4(0.f, 0.f, 0.f, 0.f);
    unsigned h0, l0, h1, l1;
    split2(v.x, v.y, h0, l0);
    split2(v.z, v.w, h1, l1);
    ((uint2*)g_XH)[i] = make_uint2(h0, h1);
    ((uint2*)g_XL)[i] = make_uint2(l0, l1);
}

__global__ void prep_w1_kernel(const float* __restrict__ W1) {
    int idx = blockIdx.x * blockDim.x + threadIdx.x;
    if (idx >= C1 * FI) return;
    int c = idx >> 8;
    int k = idx & 255;
    float v = W1[(size_t)(c >> 6) * (FI * HD) + (size_t)k * HD + (c & 63)];
    split1(v, g_W1TH[idx], g_W1TL[idx]);
}

__global__ void prep_w2_kernel(const float* __restrict__ W2) {
    int idx = blockIdx.x * blockDim.x + threadIdx.x;
    if (idx >= NC * C1) return;
    int c = idx >> 9;
    int k = idx & 511;
    float v = W2[(size_t)k * NC + c];
    split1(v, g_W2TH[idx], g_W2TL[idx]);
}

// ---------------- GEMM1: tensor-core bf16-split, fused a1 dots ----------------
// H1[N,512] = x @ W1cat.  Block 128x128, BK=16, 8 warps (4m x 2n), warp 32x64.
__global__ __launch_bounds__(256) void gemm1_mma_kernel(const float* __restrict__ a1p) {
    __shared__ unsigned Ah[128][12];
    __shared__ unsigned Al[128][12];
    __shared__ unsigned Bh[128][12];   // [col][k halves]
    __shared__ unsigned Bl[128][12];

    const int tid  = threadIdx.x;
    const int lane = tid & 31;
    const int wid  = tid >> 5;
    const int wm   = wid >> 1;
    const int wn   = wid & 1;
    const int bm   = blockIdx.x * 128;
    const int bn   = blockIdx.y * 128;

    float acc[2][8][4];
#pragma unroll
    for (int i = 0; i < 2; i++)
#pragma unroll
        for (int j = 0; j < 8; j++)
#pragma unroll
            for (int k = 0; k < 4; k++) acc[i][j][k] = 0.f;

    const unsigned aBaseH = smem_u32(Ah);
    const unsigned aBaseL = smem_u32(Al);
    const unsigned bBaseH = smem_u32(Bh);
    const unsigned bBaseL = smem_u32(Bl);

    unsigned aadrH[2], aadrL[2];
#pragma unroll
    for (int mt = 0; mt < 2; mt++) {
        int r = wm * 32 + mt * 16 + (lane & 15);
        int cb = (lane >> 4) * 16;
        aadrH[mt] = aBaseH + r * 48 + cb;
        aadrL[mt] = aBaseL + r * 48 + cb;
    }
    unsigned badrH[4], badrL[4];
#pragma unroll
    for (int np = 0; np < 4; np++) {
        int r = wn * 64 + np * 16 + ((lane >> 4) << 3) + (lane & 7);
        int cb = ((lane >> 3) & 1) * 16;
        badrH[np] = bBaseH + r * 48 + cb;
        badrL[np] = bBaseL + r * 48 + cb;
    }

    const int arow = tid >> 1;          // 0..127
    const int ach  = tid & 1;           // 16B chunk
    // global half-index bases
    size_t aIdx = (size_t)(bm + arow) * FI + ach * 8;         // + k0
    size_t bIdx = (size_t)(bn + arow) * FI + ach * 8;         // col = arow

    for (int it = 0; it < FI / 16; ++it) {
        const int k0 = it * 16;
        uint4 vah = *(const uint4*)((const unsigned short*)g_XH + aIdx + k0);
        uint4 val = *(const uint4*)((const unsigned short*)g_XL + aIdx + k0);
        uint4 vbh = *(const uint4*)(g_W1TH + bIdx + k0);
        uint4 vbl = *(const uint4*)(g_W1TL + bIdx + k0);
        *(uint4*)&Ah[arow][ach * 4] = vah;
        *(uint4*)&Al[arow][ach * 4] = val;
        *(uint4*)&Bh[arow][ach * 4] = vbh;
        *(uint4*)&Bl[arow][ach * 4] = vbl;
        __syncthreads();

        unsigned ah[2][4], al[2][4];
#pragma unroll
        for (int mt = 0; mt < 2; mt++) {
            ldm4(ah[mt][0], ah[mt][1], ah[mt][2], ah[mt][3], aadrH[mt]);
            ldm4(al[mt][0], al[mt][1], al[mt][2], al[mt][3], aadrL[mt]);
        }
#pragma unroll
        for (int np = 0; np < 4; np++) {
            unsigned bh[4], bl[4];
            ldm4(bh[0], bh[1], bh[2], bh[3], badrH[np]);
            ldm4(bl[0], bl[1], bl[2], bl[3], badrL[np]);
#pragma unroll
            for (int mt = 0; mt < 2; mt++) {
                mma16816(acc[mt][np * 2],     ah[mt], bh);
                mma16816(acc[mt][np * 2],     ah[mt], bl);
                mma16816(acc[mt][np * 2],     al[mt], bh);
                mma16816(acc[mt][np * 2 + 1], ah[mt], bh + 2);
                mma16816(acc[mt][np * 2 + 1], ah[mt], bl + 2);
                mma16816(acc[mt][np * 2 + 1], al[mt], bh + 2);
            }
        }
        __syncthreads();
    }

    // write H1
#pragma unroll
    for (int mt = 0; mt < 2; mt++) {
        int r = bm + wm * 32 + mt * 16 + (lane >> 2);
        int c = bn + wn * 64 + (lane & 3) * 2;
#pragma unroll
        for (int nt = 0; nt < 8; nt++) {
            if (r < NN) {
                float2 v0;
                v0.x = acc[mt][nt][0];
                v0.y = acc[mt][nt][1];
                *(float2*)&g_H1[(size_t)r * C1 + c + nt * 8] = v0;
            }
            if (r + 8 < NN) {
                float2 v1;
                v1.x = acc[mt][nt][2];
                v1.y = acc[mt][nt][3];
                *(float2*)&g_H1[(size_t)(r + 8) * C1 + c + nt * 8] = v1;
            }
        }
    }

    // fused a1 dots: warp wn owns head hh over its 64 cols
    const int hh = blockIdx.y * 2 + wn;
    const float* av = a1p + hh * (2 * HD);
    const float* tv = av + HD;
    float sdot[4], tdot[4];
#pragma unroll
    for (int i = 0; i < 4; i++) { sdot[i] = 0.f; tdot[i] = 0.f; }
#pragma unroll
    for (int mt = 0; mt < 2; mt++) {
#pragma unroll
        for (int nt = 0; nt < 8; nt++) {
            int cip = nt * 8 + (lane & 3) * 2;
            float a0 = __ldg(av + cip);
            float a1e = __ldg(av + cip + 1);
            float t0 = __ldg(tv + cip);
            float t1e = __ldg(tv + cip + 1);
            sdot[mt * 2 + 0] += acc[mt][nt][0] * a0 + acc[mt][nt][1] * a1e;
            tdot[mt * 2 + 0] += acc[mt][nt][0] * t0 + acc[mt][nt][1] * t1e;
            sdot[mt * 2 + 1] += acc[mt][nt][2] * a0 + acc[mt][nt][3] * a1e;
            tdot[mt * 2 + 1] += acc[mt][nt][2] * t0 + acc[mt][nt][3] * t1e;
        }
    }
#pragma unroll
    for (int i = 0; i < 4; i++) {
        sdot[i] += __shfl_xor_sync(0xffffffffu, sdot[i], 1);
        sdot[i] += __shfl_xor_sync(0xffffffffu, sdot[i], 2);
        tdot[i] += __shfl_xor_sync(0xffffffffu, tdot[i], 1);
        tdot[i] += __shfl_xor_sync(0xffffffffu, tdot[i], 2);
    }
    if ((lane & 3) == 0) {
#pragma unroll
        for (int mt = 0; mt < 2; mt++) {
#pragma unroll
            for (int hb = 0; hb < 2; hb++) {
                int r = bm + wm * 32 + mt * 16 + (lane >> 2) + hb * 8;
                if (r < NN) {
                    g_ASRC1[r * NH + hh] = sdot[mt * 2 + hb];
                    g_ATGT1[r * NH + hh] = tdot[mt * 2 + hb];
                }
            }
        }
    }
}

// ---------------- edge1 ----------------
__global__ void edge1_kernel(const int* __restrict__ src, const int* __restrict__ tgt) {
    int e = blockIdx.x * blockDim.x + threadIdx.x;
    if (e >= NE) return;
    int s = src[e];
    int t = tgt[e];
    atomicAdd(&g_CNT[s], 1);
    float4 s0 = *(const float4*)&g_ASRC1[s * NH];
    float4 s1 = *(const float4*)&g_ASRC1[s * NH + 4];
    float4 t0 = *(const float4*)&g_ATGT1[t * NH];
    float4 t1 = *(const float4*)&g_ATGT1[t * NH + 4];
    float4 e0, e1;
    e0.x = expf(lrelu(s0.x + t0.x));
    e0.y = expf(lrelu(s0.y + t0.y));
    e0.z = expf(lrelu(s0.z + t0.z));
    e0.w = expf(lrelu(s0.w + t0.w));
    e1.x = expf(lrelu(s1.x + t1.x));
    e1.y = expf(lrelu(s1.y + t1.y));
    e1.z = expf(lrelu(s1.z + t1.z));
    e1.w = expf(lrelu(s1.w + t1.w));
    *(float4*)&g_EV1[(size_t)e * NH]     = e0;
    *(float4*)&g_EV1[(size_t)e * NH + 4] = e1;
}

// ---------------- counting-sort scan ----------------
#define SBLK 512
#define NBLK 98

__global__ void scan_block_kernel() {
    __shared__ int sh[SBLK];
    int t = threadIdx.x;
    int i = blockIdx.x * SBLK + t;
    int v = (i < NN) ? g_CNT[i] : 0;
    sh[t] = v;
    __syncthreads();
#pragma unroll
    for (int off = 1; off < SBLK; off <<= 1) {
        int add = (t >= off) ? sh[t - off] : 0;
        __syncthreads();
        sh[t] += add;
        __syncthreads();
    }
    if (i < NN) g_OFFS[i] = sh[t] - v;
    if (t == SBLK - 1) g_AUX[blockIdx.x] = sh[SBLK - 1];
}

__global__ void scan_aux_kernel() {
    int run = 0;
    for (int b = 0; b < NBLK; b++) {
        int t = g_AUX[b];
        g_AUX[b] = run;
        run += t;
    }
}

__global__ void scan_add_kernel() {
    int t = threadIdx.x;
    int i = blockIdx.x * SBLK + t;
    if (i < NN) {
        int v = g_OFFS[i] + g_AUX[blockIdx.x];
        g_OFFS[i] = v;
        g_CURSOR[i] = v;
    }
    if (i == 0) g_OFFS[NN] = NE;
}

__global__ void sort_kernel(const int* __restrict__ src) {
    int e = blockIdx.x * blockDim.x + threadIdx.x;
    if (e >= NE) return;
    int s = src[e];
    int pos = atomicAdd(&g_CURSOR[s], 1);
    g_ORDER[pos] = e;
}

// ---------------- gather1: softmax-weighted gather + ELU + bf16 split ----------------
__global__ void gather1_kernel(const int* __restrict__ tgt, const float* __restrict__ b1) {
    int w = (blockIdx.x * blockDim.x + threadIdx.x) >> 5;
    int lane = threadIdx.x & 31;
    if (w >= NN) return;
    int beg = g_OFFS[w];
    int end = g_OFFS[w + 1];
    int hsel = lane >> 4;
    float den[4];
    float4 acc[4];
#pragma unroll
    for (int g = 0; g < 4; g++) {
        den[g] = 0.f;
        acc[g] = make_float4(0.f, 0.f, 0.f, 0.f);
    }
    for (int i = beg; i < end; i++) {
        int e = g_ORDER[i];
        int t = tgt[e];
        const float* hrow = g_H1 + (size_t)t * C1;
        const float* evp = g_EV1 + (size_t)e * NH;
#pragma unroll
        for (int g = 0; g < 4; g++) {
            float ev = evp[g * 2 + hsel];
            den[g] += ev;
            float4 v = *(const float4*)(hrow + g * 128 + lane * 4);
            acc[g].x += ev * v.x;
            acc[g].y += ev * v.y;
            acc[g].z += ev * v.z;
            acc[g].w += ev * v.w;
        }
    }
#pragma unroll
    for (int g = 0; g < 4; g++) {
        float r = 1.f / (den[g] + 1e-10f);
        int col = g * 128 + lane * 4;
        float4 bb = *(const float4*)&b1[col];
        float v0 = eluf(acc[g].x * r + bb.x);
        float v1 = eluf(acc[g].y * r + bb.y);
        float v2 = eluf(acc[g].z * r + bb.z);
        float v3 = eluf(acc[g].w * r + bb.w);
        unsigned h0, l0, h1, l1;
        split2(v0, v1, h0, l0);
        split2(v2, v3, h1, l1);
        size_t base = (size_t)w * C1 + col;
        *(uint2*)&g_EH[base] = make_uint2(h0, h1);
        *(uint2*)&g_EL[base] = make_uint2(l0, l1);
    }
}

// ---------------- GEMM2: tensor-core, fused alpha2 ----------------
// H2[N,40] = E[N,512] @ W2[512,40].  Block 128 rows, 8 warps each m16 x n40.
__global__ __launch_bounds__(256) void gemm2_mma_kernel(const float* __restrict__ a2) {
    __shared__ unsigned Ah[128][12];
    __shared__ unsigned Al[128][12];
    __shared__ unsigned Bh[48][12];
    __shared__ unsigned Bl[48][12];

    const int tid  = threadIdx.x;
    const int lane = tid & 31;
    const int wid  = tid >> 5;
    const int bm   = blockIdx.x * 128;

    float acc[5][4];
#pragma unroll
    for (int j = 0; j < 5; j++)
#pragma unroll
        for (int k = 0; k < 4; k++) acc[j][k] = 0.f;

    const unsigned aBaseH = smem_u32(Ah);
    const unsigned aBaseL = smem_u32(Al);
    const unsigned bBaseH = smem_u32(Bh);
    const unsigned bBaseL = smem_u32(Bl);

    unsigned aadrH, aadrL;
    {
        int r = wid * 16 + (lane & 15);
        int cb = (lane >> 4) * 16;
        aadrH = aBaseH + r * 48 + cb;
        aadrL = aBaseL + r * 48 + cb;
    }
    unsigned badrH[3], badrL[3];
#pragma unroll
    for (int np = 0; np < 3; np++) {
        int r = np * 16 + ((lane >> 4) << 3) + (lane & 7);
        int cb = ((lane >> 3) & 1) * 16;
        badrH[np] = bBaseH + r * 48 + cb;
        badrL[np] = bBaseL + r * 48 + cb;
    }

    const int arow = tid >> 1;
    const int ach  = tid & 1;
    size_t aIdx = (size_t)(bm + arow) * C1 + ach * 8;

    for (int it = 0; it < C1 / 16; ++it) {
        const int k0 = it * 16;
        uint4 vah = *(const uint4*)(g_EH + aIdx + k0);
        uint4 val = *(const uint4*)(g_EL + aIdx + k0);
        *(uint4*)&Ah[arow][ach * 4] = vah;
        *(uint4*)&Al[arow][ach * 4] = val;
        if (tid < 80) {
            int col = tid >> 1;
            int ch = tid & 1;
            size_t bi = (size_t)col * C1 + k0 + ch * 8;
            *(uint4*)&Bh[col][ch * 4] = *(const uint4*)(g_W2TH + bi);
            *(uint4*)&Bl[col][ch * 4] = *(const uint4*)(g_W2TL + bi);
        }
        __syncthreads();

        unsigned ah[4], al[4];
        ldm4(ah[0], ah[1], ah[2], ah[3], aadrH);
        ldm4(al[0], al[1], al[2], al[3], aadrL);
#pragma unroll
        for (int np = 0; np < 3; np++) {
            unsigned bh[4], bl[4];
            ldm4(bh[0], bh[1], bh[2], bh[3], badrH[np]);
            ldm4(bl[0], bl[1], bl[2], bl[3], badrL[np]);
            // frags: nt = np*2 (+1 if np<2)
            mma16816(acc[np * 2], ah, bh);
            mma16816(acc[np * 2], ah, bl);
            mma16816(acc[np * 2], al, bh);
            if (np < 2) {
                mma16816(acc[np * 2 + 1], ah, bh + 2);
                mma16816(acc[np * 2 + 1], ah, bl + 2);
                mma16816(acc[np * 2 + 1], al, bh + 2);
            }
        }
        __syncthreads();
    }

    // epilogue: write H2 + fused a2 dots (warp owns full 40-col rows)
    int r0 = bm + wid * 16 + (lane >> 2);
    int r1 = r0 + 8;
    float s0 = 0.f, s1 = 0.f, t0 = 0.f, t1 = 0.f;
#pragma unroll
    for (int nt = 0; nt < 5; nt++) {
        int c = nt * 8 + (lane & 3) * 2;
        float a0 = __ldg(a2 + c);
        float a1e = __ldg(a2 + c + 1);
        float b0 = __ldg(a2 + NC + c);
        float b1e = __ldg(a2 + NC + c + 1);
        if (r0 < NN) {
            float2 v;
            v.x = acc[nt][0];
            v.y = acc[nt][1];
            *(float2*)&g_H2[(size_t)r0 * NC + c] = v;
        }
        if (r1 < NN) {
            float2 v;
            v.x = acc[nt][2];
            v.y = acc[nt][3];
            *(float2*)&g_H2[(size_t)r1 * NC + c] = v;
        }
        s0 += acc[nt][0] * a0 + acc[nt][1] * a1e;
        t0 += acc[nt][0] * b0 + acc[nt][1] * b1e;
        s1 += acc[nt][2] * a0 + acc[nt][3] * a1e;
        t1 += acc[nt][2] * b0 + acc[nt][3] * b1e;
    }
    s0 += __shfl_xor_sync(0xffffffffu, s0, 1);
    s0 += __shfl_xor_sync(0xffffffffu, s0, 2);
    s1 += __shfl_xor_sync(0xffffffffu, s1, 1);
    s1 += __shfl_xor_sync(0xffffffffu, s1, 2);
    t0 += __shfl_xor_sync(0xffffffffu, t0, 1);
    t0 += __shfl_xor_sync(0xffffffffu, t0, 2);
    t1 += __shfl_xor_sync(0xffffffffu, t1, 1);
    t1 += __shfl_xor_sync(0xffffffffu, t1, 2);
    if ((lane & 3) == 0) {
        if (r0 < NN) {
            g_ASRC2[r0] = s0;
            g_ATGT2[r0] = t0;
        }
        if (r1 < NN) {
            g_ASRC2[r1] = s1;
            g_ATGT2[r1] = t1;
        }
    }
}

// ---------------- edge2 ----------------
__global__ void edge2_kernel(const int* __restrict__ src, const int* __restrict__ tgt) {
    int e = blockIdx.x * blockDim.x + threadIdx.x;
    if (e >= NE) return;
    int s = src[e];
    int t = tgt[e];
    g_EV2[e] = expf(lrelu(g_ASRC2[s] + g_ATGT2[t]));
}

// ---------------- gather2 ----------------
__global__ void gather2_kernel(const int* __restrict__ tgt) {
    int w = (blockIdx.x * blockDim.x + threadIdx.x) >> 5;
    int lane = threadIdx.x & 31;
    if (w >= NN) return;
    int beg = g_OFFS[w];
    int end = g_OFFS[w + 1];
    bool has2 = lane < 8;
    float acc1 = 0.f;
    float acc2 = 0.f;
    float den = 0.f;
    for (int i = beg; i < end; i++) {
        int e = g_ORDER[i];
        int t = tgt[e];
        float ev = g_EV2[e];
        den += ev;
        acc1 += ev * g_H2[t * NC + lane];
        if (has2) acc2 += ev * g_H2[t * NC + 32 + lane];
    }
    float r = 1.f / (den + 1e-10f);
    g_OUT2[w * NC + lane] = acc1 * r;
    if (has2) g_OUT2[w * NC + 32 + lane] = acc2 * r;
}

// ---------------- log_softmax ----------------
__global__ void logsm_kernel(const float* __restrict__ b2, float* __restrict__ out) {
    int w = (blockIdx.x * blockDim.x + threadIdx.x) >> 5;
    int lane = threadIdx.x & 31;
    if (w >= NN) return;
    float v1 = g_OUT2[w * NC + lane] + b2[lane];
    bool has2 = lane < 8;
    float v2 = has2 ? (g_OUT2[w * NC + 32 + lane] + b2[32 + lane]) : -3.0e38f;
    float m = wmax(fmaxf(v1, v2));
    float ssum = expf(v1 - m) + (has2 ? expf(v2 - m) : 0.f);
    ssum = wsum(ssum);
    float l = logf(ssum);
    out[w * NC + lane] = v1 - m - l;
    if (has2) out[w * NC + 32 + lane] = v2 - m - l;
}

// ---------------- launch ----------------
extern "C" void kernel_launch(void* const* d_in, const int* in_sizes, int n_in,
                              void* d_out, int out_size) {
    const float* x  = (const float*)d_in[0];
    const int*   el = (const int*)d_in[1];
    const float* W1 = (const float*)d_in[2];
    const float* a1 = (const float*)d_in[3];
    const float* b1 = (const float*)d_in[4];
    const float* W2 = (const float*)d_in[5];
    const float* a2 = (const float*)d_in[6];
    const float* b2 = (const float*)d_in[7];
    float* out = (float*)d_out;
    const int* src = el;
    const int* tgt = el + NE;

    zero_all_kernel<<<((NP - NN) * C1 + 255) / 256, 256>>>();
    prep_x_kernel<<<(NP * FI / 4 + 255) / 256, 256>>>(x);
    prep_w1_kernel<<<(C1 * FI + 255) / 256, 256>>>(W1);
    prep_w2_kernel<<<(NC * C1 + 255) / 256, 256>>>(W2);

    dim3 g1(NP / 128, C1 / 128);
    gemm1_mma_kernel<<<g1, 256>>>(a1);

    edge1_kernel<<<(NE + 255) / 256, 256>>>(src, tgt);

    scan_block_kernel<<<NBLK, SBLK>>>();
    scan_aux_kernel<<<1, 1>>>();
    scan_add_kernel<<<NBLK, SBLK>>>();
    sort_kernel<<<(NE + 255) / 256, 256>>>(src);

    int warp_grid = (NN * 32 + 255) / 256;
    gather1_kernel<<<warp_grid, 256>>>(tgt, b1);

    gemm2_mma_kernel<<<NP / 128, 256>>>(a2);
    edge2_kernel<<<(NE + 255) / 256, 256>>>(src, tgt);
    gather2_kernel<<<warp_grid, 256>>>(tgt);
    logsm_kernel<<<warp_grid, 256>>>(b2, out);
}

// round 6
// speedup vs baseline: 1.6131x; 1.0798x over previous
#include <cuda_runtime.h>
#include <cuda_bf16.h>
#include <math.h>

#define NN 50000
#define NP 50176          // padded rows (multiple of 128)
#define NE 800000
#define FI 256
#define NH 8
#define HD 64
#define C1 512
#define NC 40
#define LRELU_SLOPE 0.2f

// ---------------- static scratch ----------------
__device__ float g_H1[(size_t)NN * C1];
__device__ float g_ASRC1[NN * NH];
__device__ float g_ATGT1[NN * NH];
__device__ float g_H2[NN * NC];
__device__ float g_ASRC2[NN];
__device__ float g_ATGT2[NN];
__device__ int   g_CNT[NN];
__device__ int   g_OFFS[NN + 1];
__device__ int   g_CURSOR[NN];
__device__ int   g_TSORT[NE];
__device__ int   g_AUX[128];

// bf16-split operands
__device__ __align__(16) unsigned g_XH[(size_t)NP * FI / 2];
__device__ __align__(16) unsigned g_XL[(size_t)NP * FI / 2];
__device__ __align__(16) unsigned short g_W1TH[C1 * FI];   // [col512][k256]
__device__ __align__(16) unsigned short g_W1TL[C1 * FI];
__device__ __align__(16) unsigned short g_W2TH[NC * C1];   // [col40][k512]
__device__ __align__(16) unsigned short g_W2TL[NC * C1];
__device__ __align__(16) unsigned short g_EH[(size_t)NP * C1];  // ELU(OUT1+b1) hi
__device__ __align__(16) unsigned short g_EL[(size_t)NP * C1];  // lo

// ---------------- helpers ----------------
__device__ __forceinline__ float lrelu(float v) { return v > 0.f ? v : LRELU_SLOPE * v; }
__device__ __forceinline__ float eluf(float v)  { return v > 0.f ? v : expm1f(v); }

__device__ __forceinline__ float wsum(float v) {
#pragma unroll
    for (int o = 16; o; o >>= 1) v += __shfl_xor_sync(0xffffffffu, v, o);
    return v;
}
__device__ __forceinline__ float wmax(float v) {
#pragma unroll
    for (int o = 16; o; o >>= 1) v = fmaxf(v, __shfl_xor_sync(0xffffffffu, v, o));
    return v;
}

__device__ __forceinline__ unsigned smem_u32(const void* p) {
    return (unsigned)__cvta_generic_to_shared(p);
}

__device__ __forceinline__ void ldm4(unsigned& r0, unsigned& r1, unsigned& r2, unsigned& r3,
                                     unsigned addr) {
    asm volatile("ldmatrix.sync.aligned.m8n8.x4.shared.b16 {%0,%1,%2,%3}, [%4];"
                 : "=r"(r0), "=r"(r1), "=r"(r2), "=r"(r3) : "r"(addr));
}

__device__ __forceinline__ void mma16816(float* c, const unsigned* a, const unsigned* b) {
    asm volatile("mma.sync.aligned.m16n8k16.row.col.f32.bf16.bf16.f32 "
                 "{%0,%1,%2,%3}, {%4,%5,%6,%7}, {%8,%9}, {%0,%1,%2,%3};"
                 : "+f"(c[0]), "+f"(c[1]), "+f"(c[2]), "+f"(c[3])
                 : "r"(a[0]), "r"(a[1]), "r"(a[2]), "r"(a[3]), "r"(b[0]), "r"(b[1]));
}

__device__ __forceinline__ void split1(float x, unsigned short& h, unsigned short& l) {
    __nv_bfloat16 hb = __float2bfloat16(x);
    float r = x - __bfloat162float(hb);
    h = (unsigned short)__bfloat16_as_ushort(hb);
    l = (unsigned short)__bfloat16_as_ushort(__float2bfloat16(r));
}

__device__ __forceinline__ void split2(float x, float y, unsigned& hw, unsigned& lw) {
    unsigned short hx, lx, hy, ly;
    split1(x, hx, lx);
    split1(y, hy, ly);
    hw = (unsigned)hx | ((unsigned)hy << 16);
    lw = (unsigned)lx | ((unsigned)ly << 16);
}

// ---------------- init / prep ----------------
__global__ void zero_all_kernel() {
    int i = blockIdx.x * blockDim.x + threadIdx.x;
    if (i < NN) g_CNT[i] = 0;
    if (i < (NP - NN) * C1) {
        g_EH[(size_t)NN * C1 + i] = 0;
        g_EL[(size_t)NN * C1 + i] = 0;
    }
}

__global__ void prep_x_kernel(const float* __restrict__ x) {
    int i = blockIdx.x * blockDim.x + threadIdx.x;
    if (i >= NP * FI / 4) return;
    int row = i >> 6;
    float4 v = (row < NN) ? *(const float4*)(x + (size_t)i * 4)
                          : make_float4(0.f, 0.f, 0.f, 0.f);
    unsigned h0, l0, h1, l1;
    split2(v.x, v.y, h0, l0);
    split2(v.z, v.w, h1, l1);
    ((uint2*)g_XH)[i] = make_uint2(h0, h1);
    ((uint2*)g_XL)[i] = make_uint2(l0, l1);
}

__global__ void prep_w1_kernel(const float* __restrict__ W1) {
    int idx = blockIdx.x * blockDim.x + threadIdx.x;
    if (idx >= C1 * FI) return;
    int c = idx >> 8;
    int k = idx & 255;
    float v = W1[(size_t)(c >> 6) * (FI * HD) + (size_t)k * HD + (c & 63)];
    split1(v, g_W1TH[idx], g_W1TL[idx]);
}

__global__ void prep_w2_kernel(const float* __restrict__ W2) {
    int idx = blockIdx.x * blockDim.x + threadIdx.x;
    if (idx >= NC * C1) return;
    int c = idx >> 9;
    int k = idx & 511;
    float v = W2[(size_t)k * NC + c];
    split1(v, g_W2TH[idx], g_W2TL[idx]);
}

// ---------------- GEMM1: mma.sync bf16-split, fused a1 dots, reg-prefetch ----------------
// H1[N,512] = x @ W1cat. Block 128x128, BK=16, 8 warps (4m x 2n), warp 32x64.
__global__ __launch_bounds__(256) void gemm1_mma_kernel(const float* __restrict__ a1p) {
    __shared__ unsigned Ah[128][12];
    __shared__ unsigned Al[128][12];
    __shared__ unsigned Bh[128][12];   // [col][k halves]
    __shared__ unsigned Bl[128][12];

    const int tid  = threadIdx.x;
    const int lane = tid & 31;
    const int wid  = tid >> 5;
    const int wm   = wid >> 1;
    const int wn   = wid & 1;
    const int bm   = blockIdx.x * 128;
    const int bn   = blockIdx.y * 128;

    float acc[2][8][4];
#pragma unroll
    for (int i = 0; i < 2; i++)
#pragma unroll
        for (int j = 0; j < 8; j++)
#pragma unroll
            for (int k = 0; k < 4; k++) acc[i][j][k] = 0.f;

    const unsigned aBaseH = smem_u32(Ah);
    const unsigned aBaseL = smem_u32(Al);
    const unsigned bBaseH = smem_u32(Bh);
    const unsigned bBaseL = smem_u32(Bl);

    unsigned aadrH[2], aadrL[2];
#pragma unroll
    for (int mt = 0; mt < 2; mt++) {
        int r = wm * 32 + mt * 16 + (lane & 15);
        int cb = (lane >> 4) * 16;
        aadrH[mt] = aBaseH + r * 48 + cb;
        aadrL[mt] = aBaseL + r * 48 + cb;
    }
    unsigned badrH[4], badrL[4];
#pragma unroll
    for (int np = 0; np < 4; np++) {
        int r = wn * 64 + np * 16 + ((lane >> 4) << 3) + (lane & 7);
        int cb = ((lane >> 3) & 1) * 16;
        badrH[np] = bBaseH + r * 48 + cb;
        badrL[np] = bBaseL + r * 48 + cb;
    }

    const int arow = tid >> 1;
    const int ach  = tid & 1;
    const unsigned short* xh = (const unsigned short*)g_XH;
    const unsigned short* xl = (const unsigned short*)g_XL;
    size_t aIdx = (size_t)(bm + arow) * FI + ach * 8;
    size_t bIdx = (size_t)(bn + arow) * FI + ach * 8;

    uint4 vah = *(const uint4*)(xh + aIdx);
    uint4 val = *(const uint4*)(xl + aIdx);
    uint4 vbh = *(const uint4*)(g_W1TH + bIdx);
    uint4 vbl = *(const uint4*)(g_W1TL + bIdx);

    for (int it = 0; it < FI / 16; ++it) {
        *(uint4*)&Ah[arow][ach * 4] = vah;
        *(uint4*)&Al[arow][ach * 4] = val;
        *(uint4*)&Bh[arow][ach * 4] = vbh;
        *(uint4*)&Bl[arow][ach * 4] = vbl;
        __syncthreads();

        if (it + 1 < FI / 16) {
            const int k1 = (it + 1) * 16;
            vah = *(const uint4*)(xh + aIdx + k1);
            val = *(const uint4*)(xl + aIdx + k1);
            vbh = *(const uint4*)(g_W1TH + bIdx + k1);
            vbl = *(const uint4*)(g_W1TL + bIdx + k1);
        }

        unsigned ah[2][4], al[2][4];
#pragma unroll
        for (int mt = 0; mt < 2; mt++) {
            ldm4(ah[mt][0], ah[mt][1], ah[mt][2], ah[mt][3], aadrH[mt]);
            ldm4(al[mt][0], al[mt][1], al[mt][2], al[mt][3], aadrL[mt]);
        }
#pragma unroll
        for (int np = 0; np < 4; np++) {
            unsigned bh[4], bl[4];
            ldm4(bh[0], bh[1], bh[2], bh[3], badrH[np]);
            ldm4(bl[0], bl[1], bl[2], bl[3], badrL[np]);
#pragma unroll
            for (int mt = 0; mt < 2; mt++) {
                mma16816(acc[mt][np * 2],     ah[mt], bh);
                mma16816(acc[mt][np * 2],     ah[mt], bl);
                mma16816(acc[mt][np * 2],     al[mt], bh);
                mma16816(acc[mt][np * 2 + 1], ah[mt], bh + 2);
                mma16816(acc[mt][np * 2 + 1], ah[mt], bl + 2);
                mma16816(acc[mt][np * 2 + 1], al[mt], bh + 2);
            }
        }
        __syncthreads();
    }

    // write H1
#pragma unroll
    for (int mt = 0; mt < 2; mt++) {
        int r = bm + wm * 32 + mt * 16 + (lane >> 2);
        int c = bn + wn * 64 + (lane & 3) * 2;
#pragma unroll
        for (int nt = 0; nt < 8; nt++) {
            if (r < NN) {
                float2 v0;
                v0.x = acc[mt][nt][0];
                v0.y = acc[mt][nt][1];
                *(float2*)&g_H1[(size_t)r * C1 + c + nt * 8] = v0;
            }
            if (r + 8 < NN) {
                float2 v1;
                v1.x = acc[mt][nt][2];
                v1.y = acc[mt][nt][3];
                *(float2*)&g_H1[(size_t)(r + 8) * C1 + c + nt * 8] = v1;
            }
        }
    }

    // fused a1 dots: warp wn owns head hh over its 64 cols
    const int hh = blockIdx.y * 2 + wn;
    const float* av = a1p + hh * (2 * HD);
    const float* tv = av + HD;
    float sdot[4], tdot[4];
#pragma unroll
    for (int i = 0; i < 4; i++) { sdot[i] = 0.f; tdot[i] = 0.f; }
#pragma unroll
    for (int mt = 0; mt < 2; mt++) {
#pragma unroll
        for (int nt = 0; nt < 8; nt++) {
            int cip = nt * 8 + (lane & 3) * 2;
            float a0 = __ldg(av + cip);
            float a1e = __ldg(av + cip + 1);
            float t0 = __ldg(tv + cip);
            float t1e = __ldg(tv + cip + 1);
            sdot[mt * 2 + 0] += acc[mt][nt][0] * a0 + acc[mt][nt][1] * a1e;
            tdot[mt * 2 + 0] += acc[mt][nt][0] * t0 + acc[mt][nt][1] * t1e;
            sdot[mt * 2 + 1] += acc[mt][nt][2] * a0 + acc[mt][nt][3] * a1e;
            tdot[mt * 2 + 1] += acc[mt][nt][2] * t0 + acc[mt][nt][3] * t1e;
        }
    }
#pragma unroll
    for (int i = 0; i < 4; i++) {
        sdot[i] += __shfl_xor_sync(0xffffffffu, sdot[i], 1);
        sdot[i] += __shfl_xor_sync(0xffffffffu, sdot[i], 2);
        tdot[i] += __shfl_xor_sync(0xffffffffu, tdot[i], 1);
        tdot[i] += __shfl_xor_sync(0xffffffffu, tdot[i], 2);
    }
    if ((lane & 3) == 0) {
#pragma unroll
        for (int mt = 0; mt < 2; mt++) {
#pragma unroll
            for (int hb = 0; hb < 2; hb++) {
                int r = bm + wm * 32 + mt * 16 + (lane >> 2) + hb * 8;
                if (r < NN) {
                    g_ASRC1[r * NH + hh] = sdot[mt * 2 + hb];
                    g_ATGT1[r * NH + hh] = tdot[mt * 2 + hb];
                }
            }
        }
    }
}

// ---------------- histogram ----------------
__global__ void hist_kernel(const int* __restrict__ src) {
    int e = blockIdx.x * blockDim.x + threadIdx.x;
    if (e >= NE) return;
    atomicAdd(&g_CNT[src[e]], 1);
}

// ---------------- counting-sort scan ----------------
#define SBLK 512
#define NBLK 98

__global__ void scan_block_kernel() {
    __shared__ int sh[SBLK];
    int t = threadIdx.x;
    int i = blockIdx.x * SBLK + t;
    int v = (i < NN) ? g_CNT[i] : 0;
    sh[t] = v;
    __syncthreads();
#pragma unroll
    for (int off = 1; off < SBLK; off <<= 1) {
        int add = (t >= off) ? sh[t - off] : 0;
        __syncthreads();
        sh[t] += add;
        __syncthreads();
    }
    if (i < NN) g_OFFS[i] = sh[t] - v;
    if (t == SBLK - 1) g_AUX[blockIdx.x] = sh[SBLK - 1];
}

__global__ void scan_aux_kernel() {
    int run = 0;
    for (int b = 0; b < NBLK; b++) {
        int t = g_AUX[b];
        g_AUX[b] = run;
        run += t;
    }
}

__global__ void scan_add_kernel() {
    int t = threadIdx.x;
    int i = blockIdx.x * SBLK + t;
    if (i < NN) {
        int v = g_OFFS[i] + g_AUX[blockIdx.x];
        g_OFFS[i] = v;
        g_CURSOR[i] = v;
    }
    if (i == 0) g_OFFS[NN] = NE;
}

__global__ void sort_kernel(const int* __restrict__ src, const int* __restrict__ tgt) {
    int e = blockIdx.x * blockDim.x + threadIdx.x;
    if (e >= NE) return;
    int s = src[e];
    int pos = atomicAdd(&g_CURSOR[s], 1);
    g_TSORT[pos] = tgt[e];
}

// ---------------- gather1: fused ev + softmax gather + ELU + bf16 split ----------------
__global__ void gather1_kernel(const float* __restrict__ b1) {
    int w = (blockIdx.x * blockDim.x + threadIdx.x) >> 5;
    int lane = threadIdx.x & 31;
    if (w >= NN) return;
    int beg = g_OFFS[w];
    int end = g_OFFS[w + 1];
    int hsel = lane >> 4;
    float asrc_l = g_ASRC1[w * NH + (lane & 7)];
    float den[4];
    float4 acc[4];
#pragma unroll
    for (int g = 0; g < 4; g++) {
        den[g] = 0.f;
        acc[g] = make_float4(0.f, 0.f, 0.f, 0.f);
    }
    for (int i = beg; i < end; i++) {
        int t = g_TSORT[i];
        float atgt = g_ATGT1[t * NH + (lane & 7)];
        float ev8 = expf(lrelu(asrc_l + atgt));
        const float* hrow = g_H1 + (size_t)t * C1;
#pragma unroll
        for (int g = 0; g < 4; g++) {
            float ev = __shfl_sync(0xffffffffu, ev8, g * 2 + hsel, 8);
            den[g] += ev;
            float4 v = *(const float4*)(hrow + g * 128 + lane * 4);
            acc[g].x += ev * v.x;
            acc[g].y += ev * v.y;
            acc[g].z += ev * v.z;
            acc[g].w += ev * v.w;
        }
    }
#pragma unroll
    for (int g = 0; g < 4; g++) {
        float r = 1.f / (den[g] + 1e-10f);
        int col = g * 128 + lane * 4;
        float4 bb = *(const float4*)&b1[col];
        float v0 = eluf(acc[g].x * r + bb.x);
        float v1 = eluf(acc[g].y * r + bb.y);
        float v2 = eluf(acc[g].z * r + bb.z);
        float v3 = eluf(acc[g].w * r + bb.w);
        unsigned h0, l0, h1, l1;
        split2(v0, v1, h0, l0);
        split2(v2, v3, h1, l1);
        size_t base = (size_t)w * C1 + col;
        *(uint2*)&g_EH[base] = make_uint2(h0, h1);
        *(uint2*)&g_EL[base] = make_uint2(l0, l1);
    }
}

// ---------------- GEMM2: mma.sync, fused alpha2 ----------------
__global__ __launch_bounds__(256) void gemm2_mma_kernel(const float* __restrict__ a2) {
    __shared__ unsigned Ah[128][12];
    __shared__ unsigned Al[128][12];
    __shared__ unsigned Bh[48][12];
    __shared__ unsigned Bl[48][12];

    const int tid  = threadIdx.x;
    const int lane = tid & 31;
    const int wid  = tid >> 5;
    const int bm   = blockIdx.x * 128;

    float acc[5][4];
#pragma unroll
    for (int j = 0; j < 5; j++)
#pragma unroll
        for (int k = 0; k < 4; k++) acc[j][k] = 0.f;

    const unsigned aBaseH = smem_u32(Ah);
    const unsigned aBaseL = smem_u32(Al);
    const unsigned bBaseH = smem_u32(Bh);
    const unsigned bBaseL = smem_u32(Bl);

    unsigned aadrH, aadrL;
    {
        int r = wid * 16 + (lane & 15);
        int cb = (lane >> 4) * 16;
        aadrH = aBaseH + r * 48 + cb;
        aadrL = aBaseL + r * 48 + cb;
    }
    unsigned badrH[3], badrL[3];
#pragma unroll
    for (int np = 0; np < 3; np++) {
        int r = np * 16 + ((lane >> 4) << 3) + (lane & 7);
        int cb = ((lane >> 3) & 1) * 16;
        badrH[np] = bBaseH + r * 48 + cb;
        badrL[np] = bBaseL + r * 48 + cb;
    }

    const int arow = tid >> 1;
    const int ach  = tid & 1;
    size_t aIdx = (size_t)(bm + arow) * C1 + ach * 8;

    uint4 vah = *(const uint4*)(g_EH + aIdx);
    uint4 val = *(const uint4*)(g_EL + aIdx);

    for (int it = 0; it < C1 / 16; ++it) {
        const int k0 = it * 16;
        *(uint4*)&Ah[arow][ach * 4] = vah;
        *(uint4*)&Al[arow][ach * 4] = val;
        if (tid < 80) {
            int col = tid >> 1;
            int ch = tid & 1;
            size_t bi = (size_t)col * C1 + k0 + ch * 8;
            *(uint4*)&Bh[col][ch * 4] = *(const uint4*)(g_W2TH + bi);
            *(uint4*)&Bl[col][ch * 4] = *(const uint4*)(g_W2TL + bi);
        }
        __syncthreads();

        if (it + 1 < C1 / 16) {
            vah = *(const uint4*)(g_EH + aIdx + k0 + 16);
            val = *(const uint4*)(g_EL + aIdx + k0 + 16);
        }

        unsigned ah[4], al[4];
        ldm4(ah[0], ah[1], ah[2], ah[3], aadrH);
        ldm4(al[0], al[1], al[2], al[3], aadrL);
#pragma unroll
        for (int np = 0; np < 3; np++) {
            unsigned bh[4], bl[4];
            ldm4(bh[0], bh[1], bh[2], bh[3], badrH[np]);
            ldm4(bl[0], bl[1], bl[2], bl[3], badrL[np]);
            mma16816(acc[np * 2], ah, bh);
            mma16816(acc[np * 2], ah, bl);
            mma16816(acc[np * 2], al, bh);
            if (np < 2) {
                mma16816(acc[np * 2 + 1], ah, bh + 2);
                mma16816(acc[np * 2 + 1], ah, bl + 2);
                mma16816(acc[np * 2 + 1], al, bh + 2);
            }
        }
        __syncthreads();
    }

    int r0 = bm + wid * 16 + (lane >> 2);
    int r1 = r0 + 8;
    float s0 = 0.f, s1 = 0.f, t0 = 0.f, t1 = 0.f;
#pragma unroll
    for (int nt = 0; nt < 5; nt++) {
        int c = nt * 8 + (lane & 3) * 2;
        float a0 = __ldg(a2 + c);
        float a1e = __ldg(a2 + c + 1);
        float b0 = __ldg(a2 + NC + c);
        float b1e = __ldg(a2 + NC + c + 1);
        if (r0 < NN) {
            float2 v;
            v.x = acc[nt][0];
            v.y = acc[nt][1];
            *(float2*)&g_H2[(size_t)r0 * NC + c] = v;
        }
        if (r1 < NN) {
            float2 v;
            v.x = acc[nt][2];
            v.y = acc[nt][3];
            *(float2*)&g_H2[(size_t)r1 * NC + c] = v;
        }
        s0 += acc[nt][0] * a0 + acc[nt][1] * a1e;
        t0 += acc[nt][0] * b0 + acc[nt][1] * b1e;
        s1 += acc[nt][2] * a0 + acc[nt][3] * a1e;
        t1 += acc[nt][2] * b0 + acc[nt][3] * b1e;
    }
    s0 += __shfl_xor_sync(0xffffffffu, s0, 1);
    s0 += __shfl_xor_sync(0xffffffffu, s0, 2);
    s1 += __shfl_xor_sync(0xffffffffu, s1, 1);
    s1 += __shfl_xor_sync(0xffffffffu, s1, 2);
    t0 += __shfl_xor_sync(0xffffffffu, t0, 1);
    t0 += __shfl_xor_sync(0xffffffffu, t0, 2);
    t1 += __shfl_xor_sync(0xffffffffu, t1, 1);
    t1 += __shfl_xor_sync(0xffffffffu, t1, 2);
    if ((lane & 3) == 0) {
        if (r0 < NN) {
            g_ASRC2[r0] = s0;
            g_ATGT2[r0] = t0;
        }
        if (r1 < NN) {
            g_ASRC2[r1] = s1;
            g_ATGT2[r1] = t1;
        }
    }
}

// ---------------- gather2 + log_softmax fused ----------------
__global__ void gather2_logsm_kernel(const float* __restrict__ b2, float* __restrict__ out) {
    int w = (blockIdx.x * blockDim.x + threadIdx.x) >> 5;
    int lane = threadIdx.x & 31;
    if (w >= NN) return;
    int beg = g_OFFS[w];
    int end = g_OFFS[w + 1];
    float asrc = g_ASRC2[w];
    bool has2 = lane < 8;
    float acc1 = 0.f;
    float acc2 = 0.f;
    float den = 0.f;
    for (int i = beg; i < end; i++) {
        int t = g_TSORT[i];
        float ev = expf(lrelu(asrc + g_ATGT2[t]));
        den += ev;
        acc1 += ev * g_H2[t * NC + lane];
        if (has2) acc2 += ev * g_H2[t * NC + 32 + lane];
    }
    float r = 1.f / (den + 1e-10f);
    float v1 = acc1 * r + b2[lane];
    float v2 = has2 ? (acc2 * r + b2[32 + lane]) : -3.0e38f;
    float m = wmax(fmaxf(v1, v2));
    float ssum = expf(v1 - m) + (has2 ? expf(v2 - m) : 0.f);
    ssum = wsum(ssum);
    float l = logf(ssum);
    out[w * NC + lane] = v1 - m - l;
    if (has2) out[w * NC + 32 + lane] = v2 - m - l;
}

// ---------------- launch ----------------
extern "C" void kernel_launch(void* const* d_in, const int* in_sizes, int n_in,
                              void* d_out, int out_size) {
    const float* x  = (const float*)d_in[0];
    const int*   el = (const int*)d_in[1];
    const float* W1 = (const float*)d_in[2];
    const float* a1 = (const float*)d_in[3];
    const float* b1 = (const float*)d_in[4];
    const float* W2 = (const float*)d_in[5];
    const float* a2 = (const float*)d_in[6];
    const float* b2 = (const float*)d_in[7];
    float* out = (float*)d_out;
    const int* src = el;
    const int* tgt = el + NE;

    zero_all_kernel<<<((NP - NN) * C1 + 255) / 256, 256>>>();
    hist_kernel<<<(NE + 255) / 256, 256>>>(src);
    scan_block_kernel<<<NBLK, SBLK>>>();
    scan_aux_kernel<<<1, 1>>>();
    scan_add_kernel<<<NBLK, SBLK>>>();
    sort_kernel<<<(NE + 255) / 256, 256>>>(src, tgt);

    prep_x_kernel<<<(NP * FI / 4 + 255) / 256, 256>>>(x);
    prep_w1_kernel<<<(C1 * FI + 255) / 256, 256>>>(W1);
    prep_w2_kernel<<<(NC * C1 + 255) / 256, 256>>>(W2);

    dim3 g1(NP / 128, C1 / 128);
    gemm1_mma_kernel<<<g1, 256>>>(a1);

    int warp_grid = (NN * 32 + 255) / 256;
    gather1_kernel<<<warp_grid, 256>>>(b1);

    gemm2_mma_kernel<<<NP / 128, 256>>>(a2);
    gather2_logsm_kernel<<<warp_grid, 256>>>(b2, out);
}